// round 15
// baseline (speedup 1.0000x reference)
#include <cuda_runtime.h>
#include <cuda_fp16.h>
#include <cstdint>

// ---------------------------------------------------------------------------
// Problem constants
// ---------------------------------------------------------------------------
#define M_TOTAL   16384
#define N_TOTAL   2048
#define K_TOTAL   2048

// GEMM tiling
#define BM        256
#define BN        128
#define BK        64
#define K_ITERS   (K_TOTAL / BK)        // 32
#define STAGES    4
#define THREADS   512

#define ROW_PITCH     80
#define A_STAGE_BYTES (BM * ROW_PITCH)  // 20480
#define B_STAGE_BYTES (BN * ROW_PITCH)  // 10240
#define STAGE_BYTES   (A_STAGE_BYTES + B_STAGE_BYTES)
#define SMEM_BYTES    (STAGES * STAGE_BYTES)            // 122880

// ---------------------------------------------------------------------------
// Scratch
// ---------------------------------------------------------------------------
__device__ __align__(128) int8_t g_qx[(size_t)M_TOTAL * K_TOTAL];   // 32 MB
__device__ __align__(128) int8_t g_qw[(size_t)N_TOTAL * K_TOTAL];   // 4 MB
__device__ float g_scales[M_TOTAL];
__device__ float g_wpart[N_TOTAL];
__device__ float g_sw;
__device__ float g_inv_sw;

// ---------------------------------------------------------------------------
// PTX helpers
// ---------------------------------------------------------------------------
__device__ __forceinline__ uint32_t smem_u32(const void* p) {
    uint32_t a;
    asm("{ .reg .u64 t; cvta.to.shared.u64 t, %1; cvt.u32.u64 %0, t; }" : "=r"(a) : "l"(p));
    return a;
}
#define CP_ASYNC_16(sm, gp) \
    asm volatile("cp.async.cg.shared.global [%0], [%1], 16;" :: "r"(sm), "l"(gp) : "memory")
#define CP_COMMIT() asm volatile("cp.async.commit_group;" ::: "memory")
#define CP_WAIT2()  asm volatile("cp.async.wait_group 2;" ::: "memory")

__device__ __forceinline__ void ldmatrix_x4(uint32_t* r, uint32_t addr) {
    asm volatile("ldmatrix.sync.aligned.m8n8.x4.shared.b16 {%0,%1,%2,%3}, [%4];"
                 : "=r"(r[0]), "=r"(r[1]), "=r"(r[2]), "=r"(r[3]) : "r"(addr));
}
__device__ __forceinline__ void ldmatrix_x2(uint32_t* r, uint32_t addr) {
    asm volatile("ldmatrix.sync.aligned.m8n8.x2.shared.b16 {%0,%1}, [%2];"
                 : "=r"(r[0]), "=r"(r[1]) : "r"(addr));
}
__device__ __forceinline__ void mma_s8(int* c, const uint32_t* a, const uint32_t* b) {
    asm volatile(
        "mma.sync.aligned.m16n8k32.row.col.s32.s8.s8.s32 "
        "{%0,%1,%2,%3}, {%4,%5,%6,%7}, {%8,%9}, {%0,%1,%2,%3};"
        : "+r"(c[0]), "+r"(c[1]), "+r"(c[2]), "+r"(c[3])
        : "r"(a[0]), "r"(a[1]), "r"(a[2]), "r"(a[3]), "r"(b[0]), "r"(b[1]));
}

// ---------------------------------------------------------------------------
// Quantization helper
// ---------------------------------------------------------------------------
__device__ __forceinline__ uint32_t pack4(float4 v, float s, int lo, int hi) {
    int q0 = __float2int_rn(v.x * s); q0 = max(lo, min(hi, q0));
    int q1 = __float2int_rn(v.y * s); q1 = max(lo, min(hi, q1));
    int q2 = __float2int_rn(v.z * s); q2 = max(lo, min(hi, q2));
    int q3 = __float2int_rn(v.w * s); q3 = max(lo, min(hi, q3));
    return (uint32_t)(q0 & 255) | ((uint32_t)(q1 & 255) << 8) |
           ((uint32_t)(q2 & 255) << 16) | ((uint32_t)(q3 & 255) << 24);
}

// ---------------------------------------------------------------------------
// Kernel 1: per-row sum of |W|
// ---------------------------------------------------------------------------
__global__ void wsum_kernel(const float* __restrict__ w) {
    const int row = blockIdx.x;
    const int tid = threadIdx.x;
    const float4* wr = reinterpret_cast<const float4*>(w) + (size_t)row * 512;
    float4 a = wr[tid];
    float4 b = wr[tid + 256];
    float s = fabsf(a.x) + fabsf(a.y) + fabsf(a.z) + fabsf(a.w)
            + fabsf(b.x) + fabsf(b.y) + fabsf(b.z) + fabsf(b.w);
    #pragma unroll
    for (int o = 16; o > 0; o >>= 1) s += __shfl_xor_sync(0xffffffffu, s, o);
    __shared__ float sm[8];
    if ((tid & 31) == 0) sm[tid >> 5] = s;
    __syncthreads();
    if (tid == 0) {
        float t = sm[0];
        #pragma unroll
        for (int i = 1; i < 8; i++) t += sm[i];
        g_wpart[row] = t;
    }
}

// ---------------------------------------------------------------------------
// Kernel 2: finalize sw
// ---------------------------------------------------------------------------
__global__ void swfinal_kernel() {
    __shared__ float sm[512];
    const int tid = threadIdx.x;
    float s = 0.0f;
    for (int i = tid; i < N_TOTAL; i += 512) s += g_wpart[i];
    sm[tid] = s;
    __syncthreads();
    for (int st = 256; st > 0; st >>= 1) {
        if (tid < st) sm[tid] += sm[tid + st];
        __syncthreads();
    }
    if (tid == 0) {
        float mean = sm[0] * (1.0f / ((float)N_TOTAL * (float)K_TOTAL));
        float sw = 1.0f / fmaxf(mean, 1e-5f);
        g_sw = sw;
        g_inv_sw = 1.0f / sw;
    }
}

// ---------------------------------------------------------------------------
// Kernel 3: ternary-quantize weight
// ---------------------------------------------------------------------------
__global__ void wquant_kernel(const float* __restrict__ w) {
    const int i = blockIdx.x * blockDim.x + threadIdx.x;
    const float sw = g_sw;
    float4 v = reinterpret_cast<const float4*>(w)[i];
    reinterpret_cast<uint32_t*>(g_qw)[i] = pack4(v, sw, -1, 1);
}

// ---------------------------------------------------------------------------
// Kernel 4: per-row int8 activation quant + combined dequant scale
// ---------------------------------------------------------------------------
__global__ void xquant_kernel(const float* __restrict__ x) {
    const int row = blockIdx.x;
    const int tid = threadIdx.x;
    const float4* xr = reinterpret_cast<const float4*>(x) + (size_t)row * 512;
    float4 v0 = xr[tid];
    float4 v1 = xr[tid + 256];
    float m = fabsf(v0.x);
    m = fmaxf(m, fabsf(v0.y)); m = fmaxf(m, fabsf(v0.z)); m = fmaxf(m, fabsf(v0.w));
    m = fmaxf(m, fabsf(v1.x)); m = fmaxf(m, fabsf(v1.y));
    m = fmaxf(m, fabsf(v1.z)); m = fmaxf(m, fabsf(v1.w));
    #pragma unroll
    for (int o = 16; o > 0; o >>= 1) m = fmaxf(m, __shfl_xor_sync(0xffffffffu, m, o));
    __shared__ float sm[8];
    __shared__ float s_si;
    if ((tid & 31) == 0) sm[tid >> 5] = m;
    __syncthreads();
    if (tid == 0) {
        float mm = sm[0];
        #pragma unroll
        for (int i = 1; i < 8; i++) mm = fmaxf(mm, sm[i]);
        mm = fmaxf(mm, 1e-5f);
        float si = 127.0f / mm;
        s_si = si;
        g_scales[row] = (1.0f / si) * g_inv_sw;
    }
    __syncthreads();
    const float si = s_si;
    uint32_t* q = reinterpret_cast<uint32_t*>(g_qx) + (size_t)row * 512;
    q[tid]       = pack4(v0, si, -128, 127);
    q[tid + 256] = pack4(v1, si, -128, 127);
}

// ---------------------------------------------------------------------------
// Kernel 5: int8 mma.sync GEMM -> FP32 output (rounded through fp16)
// BM=256 x BN=128 x BK=64, 512 threads, 16 warps (4m x 4n), warp tile 64x32
// ---------------------------------------------------------------------------
__device__ __forceinline__ void load_stage(uint32_t sA, uint32_t sB,
                                           const int8_t* gA, const int8_t* gB,
                                           int tid) {
    const int r = tid >> 2;
    const int c = (tid & 3) * 16;
    CP_ASYNC_16(sA + r * ROW_PITCH + c,          gA + (size_t)r * K_TOTAL + c);
    CP_ASYNC_16(sA + (r + 128) * ROW_PITCH + c,  gA + (size_t)(r + 128) * K_TOTAL + c);
    CP_ASYNC_16(sB + r * ROW_PITCH + c,          gB + (size_t)r * K_TOTAL + c);
}

__global__ void __launch_bounds__(THREADS, 1)
gemm_kernel(float* __restrict__ out) {
    extern __shared__ char smem[];
    const uint32_t sb = smem_u32(smem);
    const int tid = threadIdx.x;
    const int wid = tid >> 5;
    const int lid = tid & 31;
    const int gid = lid >> 2;
    const int tig = lid & 3;

    const int warp_m0 = (wid & 3) * 64;
    const int warp_n0 = (wid >> 2) * 32;

    const int m0 = blockIdx.y * BM;
    const int n0 = blockIdx.x * BN;

    const int8_t* gA = g_qx + (size_t)m0 * K_TOTAL;
    const int8_t* gB = g_qw + (size_t)n0 * K_TOTAL;

    int acc[4][4][4];
    #pragma unroll
    for (int i = 0; i < 4; i++)
        #pragma unroll
        for (int j = 0; j < 4; j++)
            #pragma unroll
            for (int r = 0; r < 4; r++) acc[i][j][r] = 0;

    #pragma unroll
    for (int s = 0; s < STAGES - 1; ++s) {
        load_stage(sb + s * STAGE_BYTES, sb + s * STAGE_BYTES + A_STAGE_BYTES,
                   gA + s * BK, gB + s * BK, tid);
        CP_COMMIT();
    }

    const int a_mtx = lid >> 3;
    const int a_row = lid & 7;
    const uint32_t a_lane = (uint32_t)((warp_m0 + (a_mtx & 1) * 8 + a_row) * ROW_PITCH
                                       + (a_mtx >> 1) * 16);
    const int b_mtx = (lid >> 3) & 1;
    const int b_row = lid & 7;
    const uint32_t b_lane = (uint32_t)(A_STAGE_BYTES
                                       + (warp_n0 + b_row) * ROW_PITCH + b_mtx * 16);

    for (int it = 0; it < K_ITERS; ++it) {
        CP_WAIT2();
        __syncthreads();

        const int nxt = it + STAGES - 1;
        if (nxt < K_ITERS) {
            const uint32_t ns = sb + (uint32_t)(nxt & (STAGES - 1)) * STAGE_BYTES;
            load_stage(ns, ns + A_STAGE_BYTES, gA + nxt * BK, gB + nxt * BK, tid);
        }
        CP_COMMIT();

        const uint32_t stg = sb + (uint32_t)(it & (STAGES - 1)) * STAGE_BYTES;

        #pragma unroll
        for (int ks = 0; ks < 2; ++ks) {
            uint32_t a[4][4];
            #pragma unroll
            for (int im = 0; im < 4; ++im)
                ldmatrix_x4(a[im], stg + a_lane + im * (16 * ROW_PITCH) + ks * 32);
            uint32_t b[4][2];
            #pragma unroll
            for (int in = 0; in < 4; ++in)
                ldmatrix_x2(b[in], stg + b_lane + in * (8 * ROW_PITCH) + ks * 32);
            #pragma unroll
            for (int im = 0; im < 4; ++im)
                #pragma unroll
                for (int in = 0; in < 4; ++in)
                    mma_s8(acc[im][in], a[im], b[in]);
        }
    }

    // epilogue: dequant, round through fp16 (reference casts to float16),
    // store as FLOAT32 — the harness output buffer is fp32.
    #pragma unroll
    for (int im = 0; im < 4; ++im) {
        const int ma = m0 + warp_m0 + im * 16 + gid;
        const float s0 = g_scales[ma];
        const float s1 = g_scales[ma + 8];
        float* row0 = out + (size_t)ma * N_TOTAL;
        float* row1 = out + (size_t)(ma + 8) * N_TOTAL;
        #pragma unroll
        for (int in = 0; in < 4; ++in) {
            const int n = n0 + warp_n0 + in * 8 + tig * 2;
            const int* c = acc[im][in];
            float2 f0, f1;
            f0.x = __half2float(__float2half_rn(__int2float_rn(c[0]) * s0));
            f0.y = __half2float(__float2half_rn(__int2float_rn(c[1]) * s0));
            f1.x = __half2float(__float2half_rn(__int2float_rn(c[2]) * s1));
            f1.y = __half2float(__float2half_rn(__int2float_rn(c[3]) * s1));
            *reinterpret_cast<float2*>(row0 + n) = f0;
            *reinterpret_cast<float2*>(row1 + n) = f1;
        }
    }
}

// ---------------------------------------------------------------------------
// Host side
// ---------------------------------------------------------------------------
extern "C" void kernel_launch(void* const* d_in, const int* in_sizes, int n_in,
                              void* d_out, int out_size) {
    const float* x;
    const float* w;
    if (in_sizes[0] == M_TOTAL * K_TOTAL) {
        x = (const float*)d_in[0];
        w = (const float*)d_in[1];
    } else {
        w = (const float*)d_in[0];
        x = (const float*)d_in[1];
    }
    float* out = (float*)d_out;

    wsum_kernel<<<N_TOTAL, 256>>>(w);
    swfinal_kernel<<<1, 512>>>();
    wquant_kernel<<<(N_TOTAL * K_TOTAL / 4) / 256, 256>>>(w);
    xquant_kernel<<<M_TOTAL, 256>>>(x);

    cudaFuncSetAttribute(gemm_kernel,
                         cudaFuncAttributeMaxDynamicSharedMemorySize, SMEM_BYTES);
    gemm_kernel<<<dim3(N_TOTAL / BN, M_TOTAL / BM), THREADS, SMEM_BYTES>>>(out);
}